// round 16
// baseline (speedup 1.0000x reference)
#include <cuda_runtime.h>
#include <math.h>
#include <stdint.h>

// ---------------------------------------------------------------------------
// HashEncoderHyFluid, R14: R13 (467us; lane-pair cooperative gathers, 4-level
// batched coalesced stores, per-group shfl combines) + __launch_bounds__(256,8)
// to force 32 regs -> 8 blocks/SM = 64 warps (100% occ, was 72.7%). The kernel
// sits at the gather wavefront floor with L1tex at 93.2%; the remaining idle
// cycles are warp-starvation, which +33% eligible warps targets. The 8-reg
// cut is expected to rematerialize cheap hash ALU rather than spill (verify:
// no LDL/STL signature, L2%/DRAM% ratios unchanged vs R13).
// ---------------------------------------------------------------------------

struct Level {
    float    rf0, rf1, rf2, rf3;   // res as float32
    unsigned s1, s2, s3;           // dense strides
    unsigned mask;                 // size-1 (hashed pow2)
    unsigned size;
    int      offset;               // float offset into hash_table
    int      mode;                 // 0 dense, 1 hash+mask, 2 hash+mod
};
struct KConfig { Level lv[16]; };

#define HPRIME1 2654435761u
#define HPRIME2 805459861u
#define HPRIME3 3674653429u

__global__ __launch_bounds__(256, 8)
void hashenc_kernel(const float4* __restrict__ xyzt,
                    const float*  __restrict__ tab,
                    float*        __restrict__ out,
                    KConfig cfg, int n)
{
    int tid = blockIdx.x * 256 + threadIdx.x;
    int q = tid >> 1;              // two lanes per query
    if (q >= n) return;
    const unsigned xb = (unsigned)(tid & 1);
    const unsigned amask = __activemask();   // pair lanes exit together

    float4 X = __ldg(&xyzt[q]);
    float4* orow = reinterpret_cast<float4*>(out + (size_t)q * 32);

    // per-lane partial buffers for the current 4-level group:
    // r0..r3 = partials of the 2 levels THIS lane stores (2 feats each)
    // s0..s3 = partials of the 2 levels the PARTNER lane stores
    float r0 = 0.f, r1 = 0.f, r2 = 0.f, r3 = 0.f;
    float s0 = 0.f, s1 = 0.f, s2 = 0.f, s3 = 0.f;

    #pragma unroll 1
    for (int s = 0; s < 16; ++s) {
        Level L = cfg.lv[s];

        float px = X.x * L.rf0, py = X.y * L.rf1, pz = X.z * L.rf2, pt = X.w * L.rf3;
        float gx = floorf(px),  gy = floorf(py),  gz = floorf(pz),  gt = floorf(pt);
        float fx = px - gx,     fy = py - gy,     fz = pz - gz,     ft = pt - gt;
        unsigned cx = (unsigned)(int)gx, cy = (unsigned)(int)gy;
        unsigned cz = (unsigned)(int)gz, ct = (unsigned)(int)gt;

        float wxs = xb ? fx : (1.f - fx);
        float wy0 = 1.f - fy, wz0 = 1.f - fz, wt0 = 1.f - ft;
        float wzt[4];
        wzt[0] = wz0 * wt0;  wzt[1] = fz * wt0;  wzt[2] = wz0 * ft;  wzt[3] = fz * ft;
        float wj[8];
        #pragma unroll
        for (int k = 0; k < 4; ++k) { wj[k] = wy0 * wzt[k]; wj[4 + k] = fy * wzt[k]; }

        unsigned bx = cx + xb;
        unsigned idx[8];
        if (L.mode == 0) {
            unsigned base0 = bx + cy * L.s1 + cz * L.s2 + ct * L.s3;
            idx[0] = base0;
            idx[1] = base0 + L.s2;
            idx[2] = base0 + L.s3;
            idx[3] = base0 + L.s2 + L.s3;
            #pragma unroll
            for (int k = 0; k < 4; ++k) idx[4 + k] = idx[k] + L.s1;
        } else if (L.mode == 1) {
            unsigned hy = cy * HPRIME1, hz = cz * HPRIME2, ht = ct * HPRIME3;
            unsigned msk = L.mask;
            unsigned rzt[4] = { hz ^ ht, (hz + HPRIME2) ^ ht,
                                hz ^ (ht + HPRIME3), (hz + HPRIME2) ^ (ht + HPRIME3) };
            #pragma unroll
            for (int k = 0; k < 4; ++k) {
                idx[k]     = (bx ^ hy             ^ rzt[k]) & msk;
                idx[4 + k] = (bx ^ (hy + HPRIME1) ^ rzt[k]) & msk;
            }
        } else {
            // generic mod fallback (never taken with current constants)
            unsigned hy = cy * HPRIME1, hz = cz * HPRIME2, ht = ct * HPRIME3;
            unsigned sz = L.size;
            unsigned rzt[4] = { hz ^ ht, (hz + HPRIME2) ^ ht,
                                hz ^ (ht + HPRIME3), (hz + HPRIME2) ^ (ht + HPRIME3) };
            #pragma unroll
            for (int k = 0; k < 4; ++k) {
                idx[k]     = (bx ^ hy             ^ rzt[k]) % sz;
                idx[4 + k] = (bx ^ (hy + HPRIME1) ^ rzt[k]) % sz;
            }
        }

        const float2* t2 = reinterpret_cast<const float2*>(tab) + (L.offset >> 1);
        float p0 = 0.f, p1 = 0.f;
        #pragma unroll
        for (int k = 0; k < 8; ++k) {
            float2 f = __ldg(t2 + idx[k]);    // pair lanes hit the same 128B line
            p0 += wj[k] * f.x;
            p1 += wj[k] * f.y;
        }
        p0 *= wxs;
        p1 *= wxs;

        // buffer partial: levels 4g,4g+1 stored by even lane (slot 2g),
        // levels 4g+2,4g+3 by odd lane (slot 2g+1).
        int j  = s & 3;
        bool to_r = xb ? (j >= 2) : (j < 2);   // goes to this lane's own half?
        int  k2   = (j < 2) ? j : (j - 2);     // 0 or 1 within either half
        if (to_r) {
            if (k2 == 0) { r0 = p0; r1 = p1; }
            else         { r2 = p0; r3 = p1; }
        } else {
            if (k2 == 0) { s0 = p0; s1 = p1; }
            else         { s2 = p0; s3 = p1; }
        }

        if (j == 3) {
            // 4 shfls per group: each lane receives exactly the partner
            // partials for the levels it stores.
            float4 v;
            v.x = r0 + __shfl_xor_sync(amask, s0, 1);
            v.y = r1 + __shfl_xor_sync(amask, s1, 1);
            v.z = r2 + __shfl_xor_sync(amask, s2, 1);
            v.w = r3 + __shfl_xor_sync(amask, s3, 1);
            orow[((s >> 2) << 1) + xb] = v;   // same 128B row, 1 coalesced wf
        }
    }
}

// ---------------------------------------------------------------------------
// Host-side config: mirrors reference build_config() op-for-op in float64.
// ---------------------------------------------------------------------------
static KConfig build_cfg_host()
{
    const double minr[4] = {16.0, 16.0, 16.0, 16.0};
    const double maxr[4] = {256.0, 256.0, 256.0, 128.0};
    const long long MAXP = 524288; // 2^19

    double b[4];
    for (int d = 0; d < 4; ++d)
        b[d] = exp((log(maxr[d]) - log(minr[d])) / 15.0);

    KConfig cfg;
    long long total = 0;
    for (int s = 0; s < 16; ++s) {
        long long res[4];
        for (int d = 0; d < 4; ++d)
            res[d] = (long long)ceil(minr[d] * pow(b[d], (double)s));
        long long raw = (res[0] + 1) * (res[1] + 1) * (res[2] + 1) * (res[3] + 1);
        long long p = (raw % 8 == 0) ? raw : ((raw + 7) / 8) * 8;
        if (p > MAXP) p = MAXP;
        int dense = (raw <= p) ? 1 : 0;

        Level& L = cfg.lv[s];
        L.rf0 = (float)res[0]; L.rf1 = (float)res[1];
        L.rf2 = (float)res[2]; L.rf3 = (float)res[3];
        L.s1 = (unsigned)(res[0] + 1);
        L.s2 = (unsigned)((res[0] + 1) * (res[1] + 1));
        L.s3 = (unsigned)((res[0] + 1) * (res[1] + 1) * (res[2] + 1));
        L.size = (unsigned)p;
        L.mask = (unsigned)(p - 1);
        L.offset = (int)total;
        if (dense)                      L.mode = 0;
        else if ((p & (p - 1)) == 0)    L.mode = 1;
        else                            L.mode = 2;
        total += p * 2;  // F = 2
    }
    return cfg;
}

extern "C" void kernel_launch(void* const* d_in, const int* in_sizes, int n_in,
                              void* d_out, int out_size)
{
    static KConfig cfg = build_cfg_host();

    const float4* xyzt = (const float4*)d_in[0];
    const float*  tab  = (const float*)d_in[1];
    float*        out  = (float*)d_out;

    int n = in_sizes[0] / 4;
    long long threads = 2LL * n;
    int blocks = (int)((threads + 255) / 256);
    hashenc_kernel<<<blocks, 256>>>(xyzt, tab, out, cfg, n);
}